// round 10
// baseline (speedup 1.0000x reference)
#include <cuda_runtime.h>
#include <cuda_fp16.h>
#include <cstdint>

#define Bn 512
#define Cn 256
#define Ln 256
#define Hn 512
#define Tn 16
#define Wn 8
#define NU (Tn + Wn - 1)   // 23 distinct encode slices
#define Zn (Tn * Wn)       // 128

// ---------------- scratch (device globals) ----------------
__device__ __align__(256) __half g_ct_cat[Bn * Wn * 1024];   // [0,512)=hi, [512,1024)=lo
__device__ __align__(256) __half g_wk_half[Tn * Cn * 512];
__device__ __align__(256) __half g_pw1_half[128 * 512];
__device__ __align__(256) __half g_E_half[NU * Bn * 256];
__device__ __align__(256) __half g_P_half[(size_t)Zn * Bn * 256];
__device__ float g_pm[(size_t)Zn * 4 * Bn];
__device__ float g_ps[(size_t)Zn * 4 * Bn];
__device__ float g_diag[(size_t)Zn * Bn];
__device__ float g_h1[Bn * Wn * (Cn / 2)];
__device__ float g_mean[Cn / 2];
__device__ float g_rstd[Cn / 2];
__device__ float g_part[256];

// ======================= helpers =======================
__device__ __forceinline__ uint32_t smem_to_u32(const void* p) {
    uint32_t a;
    asm("{ .reg .u64 t; cvta.to.shared.u64 t, %1; cvt.u32.u64 %0, t; }" : "=r"(a) : "l"(p));
    return a;
}
__device__ __forceinline__ void cp16(uint32_t s, const void* g) {
    asm volatile("cp.async.cg.shared.global [%0], [%1], 16;" :: "r"(s), "l"(g));
}
// volatile: stays ordered w.r.t. barriers / other ldsm
__device__ __forceinline__ void ldsm4(uint32_t* r, uint32_t addr) {
    asm volatile("ldmatrix.sync.aligned.m8n8.x4.shared.b16 {%0,%1,%2,%3}, [%4];"
        : "=r"(r[0]), "=r"(r[1]), "=r"(r[2]), "=r"(r[3]) : "r"(addr));
}
// NON-volatile: register-only op; lets ptxas pipeline ldsm(kk+1) above mma(kk)
__device__ __forceinline__ void mma16816(float* d, const uint32_t* a, uint32_t b0, uint32_t b1) {
    asm("mma.sync.aligned.m16n8k16.row.col.f32.f16.f16.f32 "
        "{%0,%1,%2,%3}, {%4,%5,%6,%7}, {%8,%9}, {%0,%1,%2,%3};"
        : "+f"(d[0]), "+f"(d[1]), "+f"(d[2]), "+f"(d[3])
        : "r"(a[0]), "r"(a[1]), "r"(a[2]), "r"(a[3]), "r"(b0), "r"(b1));
}

struct RemapId { __device__ int operator()(int c) const { return c; } };
struct RemapH8 { __device__ int operator()(int c) const { return c < 8 ? c : c - 8; } };

// rows of 64 halves (128B) padded to 144B; conflict-free ldsm/cp
#define ROWB 144
#define SMEMC (3 * 256 * ROWB)   // 110592; 2 CTAs/SM

// ======================= 256-thread GEMM core: 128x128 tile, K-chunk 64, 3 stages =======================
template<int NCH, typename FB>
__device__ __forceinline__ void gemm_core256(
    const __half* __restrict__ baseA, int strideA,
    const __half* __restrict__ baseB, int strideB, FB remapB,
    char* smem, float (&acc)[4][4][4])
{
    constexpr int STAGE = 256 * ROWB;
    uint32_t smb = smem_to_u32(smem);
    int tid = threadIdx.x, lane = tid & 31, warp = tid >> 5;
    int wm = warp >> 2, wn = warp & 3;

#pragma unroll
    for (int mt = 0; mt < 4; mt++)
#pragma unroll
        for (int j = 0; j < 4; j++)
#pragma unroll
            for (int q = 0; q < 4; q++) acc[mt][j][q] = 0.f;

    auto issue = [&](int ch, int stg) {
        int ka = ch * 64, kb = remapB(ch) * 64;
        uint32_t s0 = smb + stg * STAGE;
#pragma unroll
        for (int i = 0; i < 4; i++) {
            int idx = tid + 256 * i, r = idx >> 3, q = idx & 7;
            cp16(s0 + r * ROWB + q * 16, baseA + (size_t)r * strideA + ka + q * 8);
        }
#pragma unroll
        for (int i = 0; i < 4; i++) {
            int idx = tid + 256 * i, r = idx >> 3, q = idx & 7;
            cp16(s0 + 128 * ROWB + r * ROWB + q * 16, baseB + (size_t)r * strideB + kb + q * 8);
        }
        asm volatile("cp.async.commit_group;");
    };

    issue(0, 0); issue(1, 1);
#pragma unroll
    for (int ch = 0; ch < NCH; ch++) {
        int stg = ch % 3;
        asm volatile("cp.async.wait_group 1;");
        __syncthreads();
        int nx = ch + 2;
        if (nx < NCH) issue(nx, nx % 3);
        else asm volatile("cp.async.commit_group;");
        uint32_t A0 = smb + stg * STAGE;
        uint32_t B0 = A0 + 128 * ROWB;
#pragma unroll
        for (int kk = 0; kk < 4; kk++) {
            uint32_t af[4][4];
#pragma unroll
            for (int mt = 0; mt < 4; mt++)
                ldsm4(af[mt], A0 + (wm * 64 + mt * 16 + (lane & 15)) * ROWB
                            + (kk * 16 + (lane >> 4) * 8) * 2);
            uint32_t bfr[2][4];
#pragma unroll
            for (int nt = 0; nt < 2; nt++) {
                int rowb = wn * 32 + nt * 16 + (lane & 7) + ((lane >> 4) << 3);
                int colb = ((lane >> 3) & 1) * 8 + kk * 16;
                ldsm4(bfr[nt], B0 + rowb * ROWB + colb * 2);
            }
#pragma unroll
            for (int mt = 0; mt < 4; mt++)
#pragma unroll
                for (int j = 0; j < 4; j++)
                    mma16816(acc[mt][j], af[mt], bfr[j >> 1][2 * (j & 1)], bfr[j >> 1][2 * (j & 1) + 1]);
        }
        __syncthreads();
    }
}

// ======================= conversion kernels =======================
__global__ void split_ct_k(const float* __restrict__ src) {   // [4096][512]
    int i = blockIdx.x * 256 + threadIdx.x;
    int row = i >> 9, col = i & 511;
    float x = src[i];
    __half h = __float2half(x);
    __half l = __float2half(x - __half2float(h));
    size_t o = (size_t)row * 1024 + col;
    g_ct_cat[o] = h; g_ct_cat[o + 512] = l;
}
__global__ void round_wk_k(const float* __restrict__ src) {   // [4096][512]
    int i = blockIdx.x * 256 + threadIdx.x;
    g_wk_half[i] = __float2half(src[i]);
}
__global__ void round_pw1_k(const float* __restrict__ src) {  // [128][512]
    int i = blockIdx.x * 256 + threadIdx.x;
    g_pw1_half[i] = __float2half(src[i]);
}

// coalesced gather
__global__ void gather_round_k(const float* __restrict__ f, const int* __restrict__ tptr) {
    __shared__ float st[256][25];
    int b = blockIdx.x;
    int tid = threadIdx.x, warp = tid >> 5, lane = tid & 31;
    int ts = *tptr;
    int basel = min(ts + 1, Ln - Wn);
#pragma unroll
    for (int c0 = 0; c0 < 256; c0 += 8) {
        int c = c0 + warp;
        if (lane < NU) {
            int l = basel + lane;
            st[c][lane] = (l < Ln) ? f[(size_t)b * Cn * Ln + (size_t)c * Ln + l] : 0.f;
        }
    }
    __syncthreads();
#pragma unroll
    for (int u = 0; u < NU; u++) {
        g_E_half[((size_t)u * Bn + b) * 256 + tid] = __float2half(st[tid][u]);
    }
}

// ======================= pred GEMM (256 thr, 128x128, K'=512) =======================
__global__ __launch_bounds__(256, 2) void pred_g(const float* __restrict__ Wkb, int z0) {
    extern __shared__ __align__(16) char sm[];
    int by = blockIdx.x;           // a tile 0..3
    int bx = blockIdx.y;           // c tile 0..1
    int z = z0 + blockIdx.z;       // 64 per launch
    int t = z >> 3, w = z & 7;
    const __half* baseA = g_ct_cat + ((size_t)(by * 128) * 8 + w) * 1024;
    const __half* baseB = g_wk_half + (size_t)(t * 256 + bx * 128) * 512;
    float acc[4][4][4];
    gemm_core256<8>(baseA, 8 * 1024, baseB, 512, RemapId(), sm, acc);

    int lane = threadIdx.x & 31, warp = threadIdx.x >> 5;
    int wm = warp >> 2, wn = warp & 3;
    uint32_t* P = (uint32_t*)g_P_half;
#pragma unroll
    for (int mt = 0; mt < 4; mt++) {
#pragma unroll
        for (int j = 0; j < 4; j++) {
            int c = bx * 128 + wn * 32 + j * 8 + (lane & 3) * 2;
            float bb0 = Wkb[t * 256 + c], bb1 = Wkb[t * 256 + c + 1];
#pragma unroll
            for (int h = 0; h < 2; h++) {
                int a = by * 128 + wm * 64 + mt * 16 + h * 8 + (lane >> 2);
                __half h0 = __float2half(acc[mt][j][h * 2 + 0] + bb0);
                __half h1 = __float2half(acc[mt][j][h * 2 + 1] + bb1);
                size_t e = ((size_t)z * 512 + a) * 256 + c;
                P[e >> 1] = (uint32_t)__half_as_ushort(h0) | ((uint32_t)__half_as_ushort(h1) << 16);
            }
        }
    }
}

// ======================= scores GEMM (256 thr, 128x128, K'=256) + softmax partials =======================
__global__ __launch_bounds__(256, 2) void scores_g(const int* __restrict__ tptr, int z0) {
    extern __shared__ __align__(16) char sm[];
    int bx = blockIdx.x;   // a tile 0..3
    int by = blockIdx.y;   // b tile 0..3
    int z = z0 + blockIdx.z;
    int t = z >> 3, w = z & 7;
    int ts = *tptr;
    int base = min(ts + 1, Ln - Wn);
    int u = min(ts + 1 + t, Ln - Wn) - base + w;
    const __half* baseA = g_E_half + ((size_t)u * 512 + by * 128) * 256;
    const __half* baseB = g_P_half + ((size_t)z * 512 + bx * 128) * 256;
    float acc[4][4][4];
    gemm_core256<4>(baseA, 256, baseB, 256, RemapId(), sm, acc);

    int tid = threadIdx.x, lane = tid & 31, warp = tid >> 5;
    int wm = warp >> 2, wn = warp & 3;
    float* smx = (float*)sm;            // [4][128]
    float* sms = (float*)(sm + 2048);
    bool dtile = (bx == by);
#pragma unroll
    for (int mt = 0; mt < 4; mt++) {
#pragma unroll
        for (int h = 0; h < 2; h++) {
            int row = wm * 64 + mt * 16 + h * 8 + (lane >> 2);
            float mx = -1e30f;
#pragma unroll
            for (int j = 0; j < 4; j++)
                mx = fmaxf(mx, fmaxf(acc[mt][j][h * 2], acc[mt][j][h * 2 + 1]));
            mx = fmaxf(mx, __shfl_xor_sync(0xFFFFFFFFu, mx, 1));
            mx = fmaxf(mx, __shfl_xor_sync(0xFFFFFFFFu, mx, 2));
            float s = 0.f;
#pragma unroll
            for (int j = 0; j < 4; j++) {
                s += __expf(acc[mt][j][h * 2] - mx);
                s += __expf(acc[mt][j][h * 2 + 1] - mx);
            }
            s += __shfl_xor_sync(0xFFFFFFFFu, s, 1);
            s += __shfl_xor_sync(0xFFFFFFFFu, s, 2);
            if ((lane & 3) == 0) { smx[wn * 128 + row] = mx; sms[wn * 128 + row] = s; }
            if (dtile) {
                int bglob = by * 128 + row;
#pragma unroll
                for (int j = 0; j < 4; j++) {
                    int aglob = bx * 128 + wn * 32 + j * 8 + (lane & 3) * 2;
                    if (aglob == bglob)
                        g_diag[(size_t)z * 512 + bglob] = acc[mt][j][h * 2];
                    else if (aglob + 1 == bglob)
                        g_diag[(size_t)z * 512 + bglob] = acc[mt][j][h * 2 + 1];
                }
            }
        }
    }
    __syncthreads();
    if (tid < 128) {
        float m0 = smx[tid], m1 = smx[128 + tid], m2 = smx[256 + tid], m3 = smx[384 + tid];
        float M = fmaxf(fmaxf(m0, m1), fmaxf(m2, m3));
        float S = sms[tid] * __expf(m0 - M) + sms[128 + tid] * __expf(m1 - M)
                + sms[256 + tid] * __expf(m2 - M) + sms[384 + tid] * __expf(m3 - M);
        size_t o = ((size_t)z * 4 + bx) * 512 + by * 128 + tid;
        g_pm[o] = M;
        g_ps[o] = S;
    }
}

// ======================= h1 GEMM (256 thr, 128x128, K'=1024, 2-term exact ct) =======================
__global__ __launch_bounds__(256, 2) void h1_g(const float* __restrict__ pb1) {
    extern __shared__ __align__(16) char sm[];
    int by = blockIdx.x;   // 0..31
    const __half* baseA = g_ct_cat + (size_t)(by * 128) * 1024;
    float acc[4][4][4];
    gemm_core256<16>(baseA, 1024, g_pw1_half, 512, RemapH8(), sm, acc);

    int lane = threadIdx.x & 31, warp = threadIdx.x >> 5;
    int wm = warp >> 2, wn = warp & 3;
#pragma unroll
    for (int mt = 0; mt < 4; mt++) {
#pragma unroll
        for (int j = 0; j < 4; j++) {
            int c = wn * 32 + j * 8 + (lane & 3) * 2;
            float bb0 = pb1[c], bb1 = pb1[c + 1];
#pragma unroll
            for (int h = 0; h < 2; h++) {
                int row = by * 128 + wm * 64 + mt * 16 + h * 8 + (lane >> 2);
                g_h1[(size_t)row * 128 + c]     = acc[mt][j][h * 2 + 0] + bb0;
                g_h1[(size_t)row * 128 + c + 1] = acc[mt][j][h * 2 + 1] + bb1;
            }
        }
    }
}

// ======================= NCE reduction =======================
__global__ void nce_combine_k() {
    int idx = blockIdx.x * 256 + threadIdx.x;   // z*512 + b
    int z = idx >> 9, b = idx & 511;
    float m[4], p[4];
#pragma unroll
    for (int i = 0; i < 4; i++) {
        m[i] = g_pm[((size_t)z * 4 + i) * 512 + b];
        p[i] = g_ps[((size_t)z * 4 + i) * 512 + b];
    }
    float M = fmaxf(fmaxf(m[0], m[1]), fmaxf(m[2], m[3]));
    float S = p[0] * expf(m[0] - M) + p[1] * expf(m[1] - M)
            + p[2] * expf(m[2] - M) + p[3] * expf(m[3] - M);
    float term = g_diag[idx] - (M + logf(S));
    __shared__ float smr[256];
    smr[threadIdx.x] = term;
    __syncthreads();
    for (int o = 128; o; o >>= 1) {
        if (threadIdx.x < o) smr[threadIdx.x] += smr[threadIdx.x + o];
        __syncthreads();
    }
    if (threadIdx.x == 0) g_part[blockIdx.x] = smr[0];
}

__global__ void nce_final_k(float* __restrict__ out) {
    __shared__ float smr[256];
    smr[threadIdx.x] = g_part[threadIdx.x];
    __syncthreads();
    for (int o = 128; o; o >>= 1) {
        if (threadIdx.x < o) smr[threadIdx.x] += smr[threadIdx.x + o];
        __syncthreads();
    }
    if (threadIdx.x == 0) out[0] = -smr[0] / (float)(Bn * Tn * Wn);
}

// ======================= BN + proj =======================
__global__ void bn_k() {
    int j = blockIdx.x;
    float s1 = 0.f, s2 = 0.f;
    for (int i = threadIdx.x; i < Bn * Wn; i += 256) {
        float v = g_h1[(size_t)i * (Cn / 2) + j];
        s1 += v; s2 += v * v;
    }
    __shared__ float a1[256], a2[256];
    a1[threadIdx.x] = s1; a2[threadIdx.x] = s2;
    __syncthreads();
    for (int o = 128; o; o >>= 1) {
        if (threadIdx.x < o) { a1[threadIdx.x] += a1[threadIdx.x + o]; a2[threadIdx.x] += a2[threadIdx.x + o]; }
        __syncthreads();
    }
    if (threadIdx.x == 0) {
        float mean = a1[0] / (float)(Bn * Wn);
        float var = a2[0] / (float)(Bn * Wn) - mean * mean;
        g_mean[j] = mean;
        g_rstd[j] = rsqrtf(var + 1e-5f);
    }
}

__global__ void proj_k(const float* __restrict__ gamma, const float* __restrict__ beta,
                       const float* __restrict__ pw2, const float* __restrict__ pb2,
                       float* __restrict__ out) {
    __shared__ float smr[Cn / 2];
    int i = blockIdx.x, t = threadIdx.x;  // blockDim = 64
#pragma unroll
    for (int r = 0; r < 2; r++) {
        int j = t + r * 64;
        float v = g_h1[(size_t)i * (Cn / 2) + j];
        v = (v - g_mean[j]) * g_rstd[j] * gamma[j] + beta[j];
        smr[j] = fmaxf(v, 0.f);
    }
    __syncthreads();
    float acc = pb2[t];
    const float* wrow = pw2 + (size_t)t * (Cn / 2);
#pragma unroll 8
    for (int jj = 0; jj < Cn / 2; jj++) acc += smr[jj] * wrow[jj];
    out[1 + (size_t)i * 64 + t] = acc;
}

// ======================= launch =======================
extern "C" void kernel_launch(void* const* d_in, const int* in_sizes, int n_in,
                              void* d_out, int out_size) {
    const float* features = (const float*)d_in[0];
    const float* c_t      = (const float*)d_in[1];
    const float* Wk_w     = (const float*)d_in[2];
    const float* Wk_b     = (const float*)d_in[3];
    const float* pw1      = (const float*)d_in[4];
    const float* pb1      = (const float*)d_in[5];
    const float* gamma    = (const float*)d_in[6];
    const float* beta     = (const float*)d_in[7];
    const float* pw2      = (const float*)d_in[8];
    const float* pb2      = (const float*)d_in[9];
    const int*   tptr     = (const int*)d_in[10];
    float* out = (float*)d_out;

    static cudaStream_t sB, sC;
    static cudaEvent_t eFork, eCt, eG, eP0, eS0, eJoin;
    static int inited = 0;
    if (!inited) {
        cudaFuncSetAttribute(pred_g, cudaFuncAttributeMaxDynamicSharedMemorySize, SMEMC);
        cudaFuncSetAttribute(scores_g, cudaFuncAttributeMaxDynamicSharedMemorySize, SMEMC);
        cudaFuncSetAttribute(h1_g, cudaFuncAttributeMaxDynamicSharedMemorySize, SMEMC);
        cudaStreamCreateWithFlags(&sB, cudaStreamNonBlocking);
        cudaStreamCreateWithFlags(&sC, cudaStreamNonBlocking);
        cudaEventCreateWithFlags(&eFork, cudaEventDisableTiming);
        cudaEventCreateWithFlags(&eCt, cudaEventDisableTiming);
        cudaEventCreateWithFlags(&eG, cudaEventDisableTiming);
        cudaEventCreateWithFlags(&eP0, cudaEventDisableTiming);
        cudaEventCreateWithFlags(&eS0, cudaEventDisableTiming);
        cudaEventCreateWithFlags(&eJoin, cudaEventDisableTiming);
        inited = 1;
    }

    // ---- fork ----
    cudaEventRecord(eFork, 0);
    cudaStreamWaitEvent(sB, eFork, 0);
    cudaStreamWaitEvent(sC, eFork, 0);

    // main: ct split -> wk round -> pred halves
    split_ct_k<<<(Bn * Wn * Hn) / 256, 256>>>(c_t);
    cudaEventRecord(eCt, 0);
    round_wk_k<<<(Tn * Cn * Hn) / 256, 256>>>(Wk_w);
    pred_g<<<dim3(4, 2, 64), 256, SMEMC>>>(Wk_b, 0);
    cudaEventRecord(eP0, 0);
    pred_g<<<dim3(4, 2, 64), 256, SMEMC>>>(Wk_b, 64);

    // side B: gather + proj head
    gather_round_k<<<Bn, 256, 0, sB>>>(features, tptr);
    cudaEventRecord(eG, sB);
    round_pw1_k<<<(128 * 512) / 256, 256, 0, sB>>>(pw1);
    cudaStreamWaitEvent(sB, eCt, 0);
    h1_g<<<32, 256, SMEMC, sB>>>(pb1);
    bn_k<<<Cn / 2, 256, 0, sB>>>();
    proj_k<<<Bn * Wn, 64, 0, sB>>>(gamma, beta, pw2, pb2, out);
    cudaEventRecord(eJoin, sB);

    // side C: scores half 0 overlaps pred half 1
    cudaStreamWaitEvent(sC, eG, 0);
    cudaStreamWaitEvent(sC, eP0, 0);
    scores_g<<<dim3(4, 4, 64), 256, SMEMC, sC>>>(tptr, 0);
    cudaEventRecord(eS0, sC);

    // main: scores half 1 -> nce
    cudaStreamWaitEvent(0, eG, 0);
    scores_g<<<dim3(4, 4, 64), 256, SMEMC>>>(tptr, 64);
    cudaStreamWaitEvent(0, eS0, 0);
    nce_combine_k<<<256, 256>>>();
    nce_final_k<<<1, 256>>>(out);

    // join
    cudaStreamWaitEvent(0, eJoin, 0);
}